// round 2
// baseline (speedup 1.0000x reference)
#include <cuda_runtime.h>
#include <math.h>
#include <stdint.h>
#include <stddef.h>

// ---------------------------------------------------------------------------
// Problem constants
// ---------------------------------------------------------------------------
#define Bn   256
#define Ln   512
#define Cn   32
#define NBn  4
#define FREQn 8
#define STEPn 4
#define Dn   512
#define Hn   1024
#define FINn 2048
#define Fn   257

// ---------------------------------------------------------------------------
// Scratch layout (floats) inside one big __device__ array (no allocations)
// ---------------------------------------------------------------------------
#define OFF_XN    0u           // [B, L, C]             4,194,304
#define OFF_MEAN  4194304u     // [B*C]                 8192
#define OFF_STD   4202496u     // [B*C]                 8192
#define OFF_KF    4210688u     // [NB][512]             2048
#define OFF_XI    4212736u     // [NB][B*L*C]           16,777,216
#define OFF_E1    20989952u    // [NB][2048*1024]       8,388,608
#define OFF_E2    29378560u    // [NB][2048*512]        4,194,304
#define OFF_XP    33572864u    // [NB][2048*512]        4,194,304
#define OFF_R     37767168u    // [NB][12][512*512]     12,582,912
#define OFF_PR    50350080u    // [NB][256*2048]        2,097,152
#define OFF_DH    52447232u    // [NB][1024*1024]       4,194,304
#define OFF_O4    56641536u    // [NB][1024*2048]       8,388,608
#define SCRATCH_TOTAL 65030144u

__device__ float g_scratch[SCRATCH_TOTAL];

// ---------------------------------------------------------------------------
// Kernel 1: instance-norm stats + normalized input
// ---------------------------------------------------------------------------
__global__ __launch_bounds__(256) void stats_kernel(
    const float* __restrict__ x, float* __restrict__ xn,
    float* __restrict__ meanA, float* __restrict__ stdA)
{
    int g = blockIdx.x * 256 + threadIdx.x;      // 0..8191  (b*32 + c)
    int b = g >> 5;
    int c = g & 31;
    const float* p = x + (size_t)b * (Ln * Cn) + c;
    float s = 0.f, sq = 0.f;
    for (int l = 0; l < Ln; l++) {
        float v = p[l * Cn];
        s += v; sq = fmaf(v, v, sq);
    }
    float mu  = s * (1.f / Ln);
    float var = sq * (1.f / Ln) - mu * mu;
    float sd  = sqrtf(var + 1e-5f);
    meanA[g] = mu;
    stdA[g]  = sd;
    float inv = 1.f / sd;
    float* q = xn + (size_t)b * (Ln * Cn) + c;
    for (int l = 0; l < Ln; l++)
        q[l * Cn] = (p[l * Cn] - mu) * inv;
}

// ---------------------------------------------------------------------------
// Kernel 2: filter taps k_nb[t] = irfft(sigmoid(mask_weights[nb]))[t]
// Exact integer phase reduction: cos(2*pi*f*t/512) with (f*t) mod 512.
// ---------------------------------------------------------------------------
__global__ __launch_bounds__(512) void filter_kernel(
    const float* __restrict__ mw, float* __restrict__ Kf)
{
    int nb = blockIdx.x;
    int t  = threadIdx.x;          // 0..511
    const float* m = mw + nb * Fn;
    float s0   = 1.f / (1.f + expf(-m[0]));
    float s256 = 1.f / (1.f + expf(-m[256]));
    float acc = s0 + ((t & 1) ? -s256 : s256);
    const float step = 6.283185307179586f / 512.f;
    for (int f = 1; f < 256; f++) {
        float sf = 1.f / (1.f + expf(-m[f]));
        int ph = (f * t) & 511;
        acc = fmaf(2.f * sf, cosf(step * (float)ph), acc);
    }
    Kf[nb * 512 + t] = acc * (1.f / 512.f);
}

// ---------------------------------------------------------------------------
// Kernel 3: circular convolution  xi[nb,b,l,c] = sum_l' k[(l-l')&511]*xn[b,l',c]
// One block per (b, nb). xn[b] tiled through smem in 2 chunks of 256 rows.
// Each thread owns (l, l+256) x all 32 channels.
// ---------------------------------------------------------------------------
__global__ __launch_bounds__(256) void conv_kernel(
    const float* __restrict__ xn, const float* __restrict__ Kf,
    float* __restrict__ xi)
{
    __shared__ float xs[256 * Cn];   // 32 KB
    __shared__ float ks[1024];       // wrapped kernel
    const int b   = blockIdx.x;
    const int nb  = blockIdx.y;
    const int tid = threadIdx.x;

    for (int i = tid; i < 1024; i += 256)
        ks[i] = Kf[nb * 512 + (i & 511)];

    const int l0 = tid, l1 = tid + 256;
    float acc0[32], acc1[32];
#pragma unroll
    for (int j = 0; j < 32; j++) { acc0[j] = 0.f; acc1[j] = 0.f; }

    for (int ch = 0; ch < 2; ch++) {
        __syncthreads();
        const float4* src = (const float4*)(xn + (size_t)b * (Ln * Cn) + ch * (256 * Cn));
        float4* dst = (float4*)xs;
        for (int i = tid; i < 2048; i += 256) dst[i] = src[i];
        __syncthreads();

        const int base = ch * 256;
        for (int lp = 0; lp < 256; lp++) {
            const int lg = base + lp;
            const float k0 = ks[l0 - lg + 512];
            const float k1 = ks[l1 - lg + 512];
            const float4* row = (const float4*)(xs + lp * Cn);
#pragma unroll
            for (int j = 0; j < 8; j++) {
                float4 xv = row[j];
                acc0[j*4+0] = fmaf(k0, xv.x, acc0[j*4+0]);
                acc0[j*4+1] = fmaf(k0, xv.y, acc0[j*4+1]);
                acc0[j*4+2] = fmaf(k0, xv.z, acc0[j*4+2]);
                acc0[j*4+3] = fmaf(k0, xv.w, acc0[j*4+3]);
                acc1[j*4+0] = fmaf(k1, xv.x, acc1[j*4+0]);
                acc1[j*4+1] = fmaf(k1, xv.y, acc1[j*4+1]);
                acc1[j*4+2] = fmaf(k1, xv.z, acc1[j*4+2]);
                acc1[j*4+3] = fmaf(k1, xv.w, acc1[j*4+3]);
            }
        }
    }

    float* o = xi + (size_t)nb * (Bn * Ln * Cn) + (size_t)b * (Ln * Cn);
    float4* o0 = (float4*)(o + l0 * Cn);
    float4* o1 = (float4*)(o + l1 * Cn);
#pragma unroll
    for (int j = 0; j < 8; j++) {
        o0[j] = make_float4(acc0[j*4+0], acc0[j*4+1], acc0[j*4+2], acc0[j*4+3]);
        o1[j] = make_float4(acc1[j*4+0], acc1[j*4+1], acc1[j*4+2], acc1[j*4+3]);
    }
}

// ---------------------------------------------------------------------------
// Generic batched SGEMM: C = op(A[MxK] * B) (+bias) (+relu), 128x128x8 tile.
// BOP: 0 = B[N,K] row-major (NT), 1 = B[K,N] row-major (NN),
//      2 = PRED gather: B[n,kf] = R_{8+s-f}[d,k], R table base in Bp[z].
// ---------------------------------------------------------------------------
struct GemmArgs {
    int M, N, K;
    const float* A[16];
    const float* Bp[16];
    const float* bias[16];
    float*       C[16];
};

template<int BOP, bool BIAS, bool RELU>
__global__ __launch_bounds__(256) void sgemm(GemmArgs ga)
{
    __shared__ float As[8][132];
    __shared__ float Bs[8][132];
    const int z = blockIdx.z;
    const float* __restrict__ A  = ga.A[z];
    const float* __restrict__ Bm = ga.Bp[z];
    float* __restrict__ C        = ga.C[z];
    const int K = ga.K, N = ga.N;
    const int tid = threadIdx.x;
    const int tx = tid & 15, ty = tid >> 4;
    const int m0 = blockIdx.y * 128, n0 = blockIdx.x * 128;
    const int arow = tid >> 1, acol = (tid & 1) * 4;

    float acc[8][8];
#pragma unroll
    for (int i = 0; i < 8; i++)
#pragma unroll
        for (int j = 0; j < 8; j++) acc[i][j] = 0.f;

    for (int k0 = 0; k0 < K; k0 += 8) {
        float4 av = *(const float4*)(A + (size_t)(m0 + arow) * K + k0 + acol);
        As[acol+0][arow] = av.x; As[acol+1][arow] = av.y;
        As[acol+2][arow] = av.z; As[acol+3][arow] = av.w;

        if (BOP == 1) {
            const int krow = tid >> 5, ncol = (tid & 31) * 4;
            float4 bv = *(const float4*)(Bm + (size_t)(k0 + krow) * N + n0 + ncol);
            *(float4*)&Bs[krow][ncol] = bv;
        } else {
            float4 bv;
            if (BOP == 0) {
                bv = *(const float4*)(Bm + (size_t)(n0 + arow) * K + k0 + acol);
            } else {
                const int n = n0 + arow, kf = k0 + acol;
                const int s = n >> 9, d = n & 511;
                const int f = kf >> 9, kl = kf & 511;
                const int t = 8 + s - f;                  // 1..11
                bv = *(const float4*)(Bm + (size_t)t * 262144 + d * 512 + kl);
            }
            Bs[acol+0][arow] = bv.x; Bs[acol+1][arow] = bv.y;
            Bs[acol+2][arow] = bv.z; Bs[acol+3][arow] = bv.w;
        }
        __syncthreads();

#pragma unroll
        for (int kk = 0; kk < 8; kk++) {
            float a[8], b[8];
            *(float4*)(a)     = *(const float4*)&As[kk][ty * 4];
            *(float4*)(a + 4) = *(const float4*)&As[kk][64 + ty * 4];
            *(float4*)(b)     = *(const float4*)&Bs[kk][tx * 4];
            *(float4*)(b + 4) = *(const float4*)&Bs[kk][64 + tx * 4];
#pragma unroll
            for (int i = 0; i < 8; i++)
#pragma unroll
                for (int j = 0; j < 8; j++)
                    acc[i][j] = fmaf(a[i], b[j], acc[i][j]);
        }
        __syncthreads();
    }

#pragma unroll
    for (int i = 0; i < 8; i++) {
        const int m = m0 + ((i < 4) ? (ty * 4 + i) : (64 + ty * 4 + (i - 4)));
#pragma unroll
        for (int jj = 0; jj < 2; jj++) {
            const int n = n0 + ((jj == 0) ? tx * 4 : 64 + tx * 4);
            float4 v;
            v.x = acc[i][jj*4+0]; v.y = acc[i][jj*4+1];
            v.z = acc[i][jj*4+2]; v.w = acc[i][jj*4+3];
            if (BIAS) {
                const float* bb = ga.bias[z];
                v.x += bb[n]; v.y += bb[n+1]; v.z += bb[n+2]; v.w += bb[n+3];
            }
            if (RELU) {
                v.x = fmaxf(v.x, 0.f); v.y = fmaxf(v.y, 0.f);
                v.z = fmaxf(v.z, 0.f); v.w = fmaxf(v.w, 0.f);
            }
            *(float4*)(C + (size_t)m * N + n) = v;
        }
    }
}

// ---------------------------------------------------------------------------
// LayerNorm over last dim (512). One warp per row. Rows = [NB][B][STEP].
// ---------------------------------------------------------------------------
__global__ __launch_bounds__(256) void ln_kernel(
    float* __restrict__ Pr, const float* __restrict__ g, const float* __restrict__ bta)
{
    const int warp = threadIdx.x >> 5, lane = threadIdx.x & 31;
    const int row = blockIdx.x * 8 + warp;          // 0..4095
    const int nb  = row >> 10;                      // 1024 rows per block-idx
    float* p = Pr + (size_t)row * Dn;
    float v[16];
    float s = 0.f, sq = 0.f;
#pragma unroll
    for (int i = 0; i < 16; i++) {
        v[i] = p[lane + 32 * i];
        s += v[i]; sq = fmaf(v[i], v[i], sq);
    }
#pragma unroll
    for (int off = 16; off > 0; off >>= 1) {
        s  += __shfl_xor_sync(0xFFFFFFFFu, s,  off);
        sq += __shfl_xor_sync(0xFFFFFFFFu, sq, off);
    }
    float mu  = s * (1.f / Dn);
    float var = sq * (1.f / Dn) - mu * mu;
    float r   = rsqrtf(var + 1e-5f);
    const float* gg = g   + nb * Dn;
    const float* bb = bta + nb * Dn;
#pragma unroll
    for (int i = 0; i < 16; i++) {
        int d = lane + 32 * i;
        p[d] = fmaf((v[i] - mu) * r, gg[d], bb[d]);
    }
}

// ---------------------------------------------------------------------------
// Final: out = (sum_nb O4) * std + mean, with the (b, s*64+p, c) reshape.
// ---------------------------------------------------------------------------
__global__ __launch_bounds__(256) void final_kernel(
    const float* __restrict__ O4, const float* __restrict__ meanA,
    const float* __restrict__ stdA, float* __restrict__ out)
{
    int idx = blockIdx.x * 256 + threadIdx.x;       // < 2,097,152
    int b   = idx >> 13;
    int s   = (idx >> 11) & 3;
    int col = idx & 2047;                            // p*32 + c
    int c   = idx & 31;
    size_t m = (size_t)(b * 4 + s) * 2048 + col;
    const size_t str = (size_t)1024 * 2048;
    float v = O4[m] + O4[m + str] + O4[m + 2 * str] + O4[m + 3 * str];
    int bc = b * 32 + c;
    out[idx] = fmaf(v, stdA[bc], meanA[bc]);
}

// ---------------------------------------------------------------------------
// Launcher
// ---------------------------------------------------------------------------
extern "C" void kernel_launch(void* const* d_in, const int* in_sizes, int n_in,
                              void* d_out, int out_size)
{
    (void)in_sizes; (void)n_in; (void)out_size;
    const float* x_enc = (const float*)d_in[0];
    const float* maskw = (const float*)d_in[4];
    const float* ew1   = (const float*)d_in[5];
    const float* eb1   = (const float*)d_in[6];
    const float* ew2   = (const float*)d_in[7];
    const float* eb2   = (const float*)d_in[8];
    const float* wxh   = (const float*)d_in[9];
    const float* whh   = (const float*)d_in[10];
    const float* lng   = (const float*)d_in[11];
    const float* lnbta = (const float*)d_in[12];
    const float* dw1   = (const float*)d_in[13];
    const float* db1   = (const float*)d_in[14];
    const float* dw2   = (const float*)d_in[15];
    const float* db2   = (const float*)d_in[16];
    float* out = (float*)d_out;

    float* S = nullptr;
    cudaGetSymbolAddress((void**)&S, g_scratch);

    float* xn   = S + OFF_XN;
    float* mnA  = S + OFF_MEAN;
    float* sdA  = S + OFF_STD;
    float* Kf   = S + OFF_KF;
    float* XI   = S + OFF_XI;
    float* E1   = S + OFF_E1;
    float* E2   = S + OFF_E2;
    float* XP   = S + OFF_XP;
    float* Rb   = S + OFF_R;
    float* PR   = S + OFF_PR;
    float* DH   = S + OFF_DH;
    float* O4   = S + OFF_O4;

    const size_t MSZ = 512 * 512;   // one 512x512 matrix
    auto Rp = [&](int nb, int t) -> float* { return Rb + ((size_t)nb * 12 + t) * MSZ; };

    stats_kernel<<<32, 256>>>(x_enc, xn, mnA, sdA);
    filter_kernel<<<4, 512>>>(maskw, Kf);

    // R_1 = whh (copy into power table)
    for (int nb = 0; nb < 4; nb++)
        cudaMemcpyAsync(Rp(nb, 1), whh + (size_t)nb * MSZ, MSZ * sizeof(float),
                        cudaMemcpyDeviceToDevice, 0);

    GemmArgs ga;
    // --- matrix powers R_t = whh^t, t = 2..11 (4 doubling launches, NN) ---
    ga.M = 512; ga.N = 512; ga.K = 512;
    for (int nb = 0; nb < 4; nb++) {
        ga.A[nb] = Rp(nb, 1); ga.Bp[nb] = Rp(nb, 1); ga.C[nb] = Rp(nb, 2);
    }
    sgemm<1, false, false><<<dim3(4, 4, 4), 256>>>(ga);

    for (int nb = 0; nb < 4; nb++)
        for (int j = 0; j < 2; j++) {
            int z = nb * 2 + j;
            ga.A[z] = Rp(nb, 2); ga.Bp[z] = Rp(nb, 1 + j); ga.C[z] = Rp(nb, 3 + j);
        }
    sgemm<1, false, false><<<dim3(4, 4, 8), 256>>>(ga);

    for (int nb = 0; nb < 4; nb++)
        for (int j = 0; j < 4; j++) {
            int z = nb * 4 + j;
            ga.A[z] = Rp(nb, 4); ga.Bp[z] = Rp(nb, 1 + j); ga.C[z] = Rp(nb, 5 + j);
        }
    sgemm<1, false, false><<<dim3(4, 4, 16), 256>>>(ga);

    for (int nb = 0; nb < 4; nb++)
        for (int j = 0; j < 3; j++) {
            int z = nb * 3 + j;
            ga.A[z] = Rp(nb, 8); ga.Bp[z] = Rp(nb, 1 + j); ga.C[z] = Rp(nb, 9 + j);
        }
    sgemm<1, false, false><<<dim3(4, 4, 12), 256>>>(ga);

    // --- Fourier filter as circular conv ---
    conv_kernel<<<dim3(256, 4), 256>>>(xn, Kf, XI);

    // --- encoder L1: relu(res @ ew1^T + b1): [2048x2048]x[1024x2048]^T ---
    ga.M = 2048; ga.N = 1024; ga.K = 2048;
    for (int nb = 0; nb < 4; nb++) {
        ga.A[nb]    = XI + (size_t)nb * (2048u * 2048u);
        ga.Bp[nb]   = ew1 + (size_t)nb * (1024u * 2048u);
        ga.bias[nb] = eb1 + (size_t)nb * 1024u;
        ga.C[nb]    = E1 + (size_t)nb * (2048u * 1024u);
    }
    sgemm<0, true, true><<<dim3(8, 16, 4), 256>>>(ga);

    // --- encoder L2: [2048x1024]x[512x1024]^T ---
    ga.M = 2048; ga.N = 512; ga.K = 1024;
    for (int nb = 0; nb < 4; nb++) {
        ga.A[nb]    = E1 + (size_t)nb * (2048u * 1024u);
        ga.Bp[nb]   = ew2 + (size_t)nb * (512u * 1024u);
        ga.bias[nb] = eb2 + (size_t)nb * 512u;
        ga.C[nb]    = E2 + (size_t)nb * (2048u * 512u);
    }
    sgemm<0, true, false><<<dim3(4, 16, 4), 256>>>(ga);

    // --- XP = E2 @ wxh^T ---
    ga.M = 2048; ga.N = 512; ga.K = 512;
    for (int nb = 0; nb < 4; nb++) {
        ga.A[nb]  = E2 + (size_t)nb * (2048u * 512u);
        ga.Bp[nb] = wxh + (size_t)nb * MSZ;
        ga.C[nb]  = XP + (size_t)nb * (2048u * 512u);
    }
    sgemm<0, false, false><<<dim3(4, 16, 4), 256>>>(ga);

    // --- RNN + free-run folded: preds = XPc[256x4096] @ gathered-R[4096x2048] ---
    ga.M = 256; ga.N = 2048; ga.K = 4096;
    for (int nb = 0; nb < 4; nb++) {
        ga.A[nb]  = XP + (size_t)nb * (2048u * 512u);   // viewed [256, 4096]
        ga.Bp[nb] = Rb + (size_t)nb * 12 * MSZ;          // R table base
        ga.C[nb]  = PR + (size_t)nb * (256u * 2048u);
    }
    sgemm<2, false, false><<<dim3(16, 2, 4), 256>>>(ga);

    // --- LayerNorm ---
    ln_kernel<<<512, 256>>>(PR, lng, lnbta);

    // --- decoder L1: relu(P @ dw1^T + b1): [1024x512]x[1024x512]^T ---
    ga.M = 1024; ga.N = 1024; ga.K = 512;
    for (int nb = 0; nb < 4; nb++) {
        ga.A[nb]    = PR + (size_t)nb * (256u * 2048u);  // [1024, 512]
        ga.Bp[nb]   = dw1 + (size_t)nb * (1024u * 512u);
        ga.bias[nb] = db1 + (size_t)nb * 1024u;
        ga.C[nb]    = DH + (size_t)nb * (1024u * 1024u);
    }
    sgemm<0, true, true><<<dim3(8, 8, 4), 256>>>(ga);

    // --- decoder L2: [1024x1024]x[2048x1024]^T ---
    ga.M = 1024; ga.N = 2048; ga.K = 1024;
    for (int nb = 0; nb < 4; nb++) {
        ga.A[nb]    = DH + (size_t)nb * (1024u * 1024u);
        ga.Bp[nb]   = dw2 + (size_t)nb * (2048u * 1024u);
        ga.bias[nb] = db2 + (size_t)nb * 2048u;
        ga.C[nb]    = O4 + (size_t)nb * (1024u * 2048u);
    }
    sgemm<0, true, false><<<dim3(16, 8, 4), 256>>>(ga);

    // --- final combine ---
    final_kernel<<<8192, 256>>>(O4, mnA, sdA, out);
}

// round 3
// speedup vs baseline: 1.0025x; 1.0025x over previous
#include <cuda_runtime.h>
#include <math.h>
#include <stdint.h>
#include <stddef.h>

// ---------------------------------------------------------------------------
// Problem constants
// ---------------------------------------------------------------------------
#define Bn   256
#define Ln   512
#define Cn   32
#define NBn  4
#define FREQn 8
#define STEPn 4
#define Dn   512
#define Hn   1024
#define FINn 2048
#define Fn   257

// ---------------------------------------------------------------------------
// Scratch layout (floats) inside one big __device__ array (no allocations)
// ---------------------------------------------------------------------------
#define OFF_XN    0u           // [B, L, C]             4,194,304
#define OFF_MEAN  4194304u     // [B*C]                 8192
#define OFF_STD   4202496u     // [B*C]                 8192
#define OFF_KF    4210688u     // [NB][512]             2048
#define OFF_XI    4212736u     // [NB][B*L*C]           16,777,216
#define OFF_E1    20989952u    // [NB][2048*1024]       8,388,608
#define OFF_E2    29378560u    // [NB][2048*512]        4,194,304
#define OFF_XP    33572864u    // [NB][2048*512]        4,194,304
#define OFF_R     37767168u    // [NB][12][512*512]     12,582,912
#define OFF_PR    50350080u    // [NB][256*2048]        2,097,152
#define OFF_DH    52447232u    // [NB][1024*1024]       4,194,304
#define OFF_O4    56641536u    // [NB][1024*2048]       8,388,608
#define SCRATCH_TOTAL 65030144u

__device__ float g_scratch[SCRATCH_TOTAL];

// ---------------------------------------------------------------------------
// Kernel 1: instance-norm stats + normalized input
// ---------------------------------------------------------------------------
__global__ __launch_bounds__(256) void stats_kernel(
    const float* __restrict__ x, float* __restrict__ xn,
    float* __restrict__ meanA, float* __restrict__ stdA)
{
    int g = blockIdx.x * 256 + threadIdx.x;      // 0..8191  (b*32 + c)
    int b = g >> 5;
    int c = g & 31;
    const float* p = x + (size_t)b * (Ln * Cn) + c;
    float s = 0.f, sq = 0.f;
    for (int l = 0; l < Ln; l++) {
        float v = p[l * Cn];
        s += v; sq = fmaf(v, v, sq);
    }
    float mu  = s * (1.f / Ln);
    float var = sq * (1.f / Ln) - mu * mu;
    float sd  = sqrtf(var + 1e-5f);
    meanA[g] = mu;
    stdA[g]  = sd;
    float inv = 1.f / sd;
    float* q = xn + (size_t)b * (Ln * Cn) + c;
    for (int l = 0; l < Ln; l++)
        q[l * Cn] = (p[l * Cn] - mu) * inv;
}

// ---------------------------------------------------------------------------
// Kernel 2: filter taps k_nb[t] = irfft(sigmoid(mask_weights[nb]))[t]
// Exact integer phase reduction: cos(2*pi*f*t/512) with (f*t) mod 512.
// ---------------------------------------------------------------------------
__global__ __launch_bounds__(512) void filter_kernel(
    const float* __restrict__ mw, float* __restrict__ Kf)
{
    int nb = blockIdx.x;
    int t  = threadIdx.x;          // 0..511
    const float* m = mw + nb * Fn;
    float s0   = 1.f / (1.f + expf(-m[0]));
    float s256 = 1.f / (1.f + expf(-m[256]));
    float acc = s0 + ((t & 1) ? -s256 : s256);
    const float step = 6.283185307179586f / 512.f;
    for (int f = 1; f < 256; f++) {
        float sf = 1.f / (1.f + expf(-m[f]));
        int ph = (f * t) & 511;
        acc = fmaf(2.f * sf, cosf(step * (float)ph), acc);
    }
    Kf[nb * 512 + t] = acc * (1.f / 512.f);
}

// ---------------------------------------------------------------------------
// Kernel 3: circular convolution  xi[nb,b,l,c] = sum_l' k[(l-l')&511]*xn[b,l',c]
// One block per (b, nb). xn[b] tiled through smem in 2 chunks of 256 rows.
// Each thread owns (l, l+256) x all 32 channels.
// ---------------------------------------------------------------------------
__global__ __launch_bounds__(256) void conv_kernel(
    const float* __restrict__ xn, const float* __restrict__ Kf,
    float* __restrict__ xi)
{
    __shared__ float xs[256 * Cn];   // 32 KB
    __shared__ float ks[1024];       // wrapped kernel
    const int b   = blockIdx.x;
    const int nb  = blockIdx.y;
    const int tid = threadIdx.x;

    for (int i = tid; i < 1024; i += 256)
        ks[i] = Kf[nb * 512 + (i & 511)];

    const int l0 = tid, l1 = tid + 256;
    float acc0[32], acc1[32];
#pragma unroll
    for (int j = 0; j < 32; j++) { acc0[j] = 0.f; acc1[j] = 0.f; }

    for (int ch = 0; ch < 2; ch++) {
        __syncthreads();
        const float4* src = (const float4*)(xn + (size_t)b * (Ln * Cn) + ch * (256 * Cn));
        float4* dst = (float4*)xs;
        for (int i = tid; i < 2048; i += 256) dst[i] = src[i];
        __syncthreads();

        const int base = ch * 256;
        for (int lp = 0; lp < 256; lp++) {
            const int lg = base + lp;
            const float k0 = ks[l0 - lg + 512];
            const float k1 = ks[l1 - lg + 512];
            const float4* row = (const float4*)(xs + lp * Cn);
#pragma unroll
            for (int j = 0; j < 8; j++) {
                float4 xv = row[j];
                acc0[j*4+0] = fmaf(k0, xv.x, acc0[j*4+0]);
                acc0[j*4+1] = fmaf(k0, xv.y, acc0[j*4+1]);
                acc0[j*4+2] = fmaf(k0, xv.z, acc0[j*4+2]);
                acc0[j*4+3] = fmaf(k0, xv.w, acc0[j*4+3]);
                acc1[j*4+0] = fmaf(k1, xv.x, acc1[j*4+0]);
                acc1[j*4+1] = fmaf(k1, xv.y, acc1[j*4+1]);
                acc1[j*4+2] = fmaf(k1, xv.z, acc1[j*4+2]);
                acc1[j*4+3] = fmaf(k1, xv.w, acc1[j*4+3]);
            }
        }
    }

    float* o = xi + (size_t)nb * (Bn * Ln * Cn) + (size_t)b * (Ln * Cn);
    float4* o0 = (float4*)(o + l0 * Cn);
    float4* o1 = (float4*)(o + l1 * Cn);
#pragma unroll
    for (int j = 0; j < 8; j++) {
        o0[j] = make_float4(acc0[j*4+0], acc0[j*4+1], acc0[j*4+2], acc0[j*4+3]);
        o1[j] = make_float4(acc1[j*4+0], acc1[j*4+1], acc1[j*4+2], acc1[j*4+3]);
    }
}

// ---------------------------------------------------------------------------
// Generic batched SGEMM: C = op(A[MxK] * B) (+bias) (+relu), 128x128x8 tile.
// BOP: 0 = B[N,K] row-major (NT), 1 = B[K,N] row-major (NN),
//      2 = PRED gather: B[n,kf] = R_{8+s-f}[d,k], R table base in Bp[z].
// ---------------------------------------------------------------------------
struct GemmArgs {
    int M, N, K;
    const float* A[16];
    const float* Bp[16];
    const float* bias[16];
    float*       C[16];
};

template<int BOP, bool BIAS, bool RELU>
__global__ __launch_bounds__(256) void sgemm(GemmArgs ga)
{
    __shared__ float As[8][132];
    __shared__ float Bs[8][132];
    const int z = blockIdx.z;
    const float* __restrict__ A  = ga.A[z];
    const float* __restrict__ Bm = ga.Bp[z];
    float* __restrict__ C        = ga.C[z];
    const int K = ga.K, N = ga.N;
    const int tid = threadIdx.x;
    const int tx = tid & 15, ty = tid >> 4;
    const int m0 = blockIdx.y * 128, n0 = blockIdx.x * 128;
    const int arow = tid >> 1, acol = (tid & 1) * 4;

    float acc[8][8];
#pragma unroll
    for (int i = 0; i < 8; i++)
#pragma unroll
        for (int j = 0; j < 8; j++) acc[i][j] = 0.f;

    for (int k0 = 0; k0 < K; k0 += 8) {
        float4 av = *(const float4*)(A + (size_t)(m0 + arow) * K + k0 + acol);
        As[acol+0][arow] = av.x; As[acol+1][arow] = av.y;
        As[acol+2][arow] = av.z; As[acol+3][arow] = av.w;

        if (BOP == 1) {
            const int krow = tid >> 5, ncol = (tid & 31) * 4;
            float4 bv = *(const float4*)(Bm + (size_t)(k0 + krow) * N + n0 + ncol);
            *(float4*)&Bs[krow][ncol] = bv;
        } else {
            float4 bv;
            if (BOP == 0) {
                bv = *(const float4*)(Bm + (size_t)(n0 + arow) * K + k0 + acol);
            } else {
                const int n = n0 + arow, kf = k0 + acol;
                const int s = n >> 9, d = n & 511;
                const int f = kf >> 9, kl = kf & 511;
                const int t = 8 + s - f;                  // 1..11
                bv = *(const float4*)(Bm + (size_t)t * 262144 + d * 512 + kl);
            }
            Bs[acol+0][arow] = bv.x; Bs[acol+1][arow] = bv.y;
            Bs[acol+2][arow] = bv.z; Bs[acol+3][arow] = bv.w;
        }
        __syncthreads();

#pragma unroll
        for (int kk = 0; kk < 8; kk++) {
            float a[8], b[8];
            *(float4*)(a)     = *(const float4*)&As[kk][ty * 4];
            *(float4*)(a + 4) = *(const float4*)&As[kk][64 + ty * 4];
            *(float4*)(b)     = *(const float4*)&Bs[kk][tx * 4];
            *(float4*)(b + 4) = *(const float4*)&Bs[kk][64 + tx * 4];
#pragma unroll
            for (int i = 0; i < 8; i++)
#pragma unroll
                for (int j = 0; j < 8; j++)
                    acc[i][j] = fmaf(a[i], b[j], acc[i][j]);
        }
        __syncthreads();
    }

#pragma unroll
    for (int i = 0; i < 8; i++) {
        const int m = m0 + ((i < 4) ? (ty * 4 + i) : (64 + ty * 4 + (i - 4)));
#pragma unroll
        for (int jj = 0; jj < 2; jj++) {
            const int n = n0 + ((jj == 0) ? tx * 4 : 64 + tx * 4);
            float4 v;
            v.x = acc[i][jj*4+0]; v.y = acc[i][jj*4+1];
            v.z = acc[i][jj*4+2]; v.w = acc[i][jj*4+3];
            if (BIAS) {
                const float* bb = ga.bias[z];
                v.x += bb[n]; v.y += bb[n+1]; v.z += bb[n+2]; v.w += bb[n+3];
            }
            if (RELU) {
                v.x = fmaxf(v.x, 0.f); v.y = fmaxf(v.y, 0.f);
                v.z = fmaxf(v.z, 0.f); v.w = fmaxf(v.w, 0.f);
            }
            *(float4*)(C + (size_t)m * N + n) = v;
        }
    }
}

// ---------------------------------------------------------------------------
// LayerNorm over last dim (512). One warp per row. Rows = [NB][B][STEP].
// ---------------------------------------------------------------------------
__global__ __launch_bounds__(256) void ln_kernel(
    float* __restrict__ Pr, const float* __restrict__ g, const float* __restrict__ bta)
{
    const int warp = threadIdx.x >> 5, lane = threadIdx.x & 31;
    const int row = blockIdx.x * 8 + warp;          // 0..4095
    const int nb  = row >> 10;                      // 1024 rows per block-idx
    float* p = Pr + (size_t)row * Dn;
    float v[16];
    float s = 0.f, sq = 0.f;
#pragma unroll
    for (int i = 0; i < 16; i++) {
        v[i] = p[lane + 32 * i];
        s += v[i]; sq = fmaf(v[i], v[i], sq);
    }
#pragma unroll
    for (int off = 16; off > 0; off >>= 1) {
        s  += __shfl_xor_sync(0xFFFFFFFFu, s,  off);
        sq += __shfl_xor_sync(0xFFFFFFFFu, sq, off);
    }
    float mu  = s * (1.f / Dn);
    float var = sq * (1.f / Dn) - mu * mu;
    float r   = rsqrtf(var + 1e-5f);
    const float* gg = g   + nb * Dn;
    const float* bb = bta + nb * Dn;
#pragma unroll
    for (int i = 0; i < 16; i++) {
        int d = lane + 32 * i;
        p[d] = fmaf((v[i] - mu) * r, gg[d], bb[d]);
    }
}

// ---------------------------------------------------------------------------
// Final: out = (sum_nb O4) * std + mean, with the (b, s*64+p, c) reshape.
// ---------------------------------------------------------------------------
__global__ __launch_bounds__(256) void final_kernel(
    const float* __restrict__ O4, const float* __restrict__ meanA,
    const float* __restrict__ stdA, float* __restrict__ out)
{
    int idx = blockIdx.x * 256 + threadIdx.x;       // < 2,097,152
    int b   = idx >> 13;
    int s   = (idx >> 11) & 3;
    int col = idx & 2047;                            // p*32 + c
    int c   = idx & 31;
    size_t m = (size_t)(b * 4 + s) * 2048 + col;
    const size_t str = (size_t)1024 * 2048;
    float v = O4[m] + O4[m + str] + O4[m + 2 * str] + O4[m + 3 * str];
    int bc = b * 32 + c;
    out[idx] = fmaf(v, stdA[bc], meanA[bc]);
}

// ---------------------------------------------------------------------------
// Launcher
// ---------------------------------------------------------------------------
extern "C" void kernel_launch(void* const* d_in, const int* in_sizes, int n_in,
                              void* d_out, int out_size)
{
    (void)in_sizes; (void)n_in; (void)out_size;
    const float* x_enc = (const float*)d_in[0];
    const float* maskw = (const float*)d_in[4];
    const float* ew1   = (const float*)d_in[5];
    const float* eb1   = (const float*)d_in[6];
    const float* ew2   = (const float*)d_in[7];
    const float* eb2   = (const float*)d_in[8];
    const float* wxh   = (const float*)d_in[9];
    const float* whh   = (const float*)d_in[10];
    const float* lng   = (const float*)d_in[11];
    const float* lnbta = (const float*)d_in[12];
    const float* dw1   = (const float*)d_in[13];
    const float* db1   = (const float*)d_in[14];
    const float* dw2   = (const float*)d_in[15];
    const float* db2   = (const float*)d_in[16];
    float* out = (float*)d_out;

    float* S = nullptr;
    cudaGetSymbolAddress((void**)&S, g_scratch);

    float* xn   = S + OFF_XN;
    float* mnA  = S + OFF_MEAN;
    float* sdA  = S + OFF_STD;
    float* Kf   = S + OFF_KF;
    float* XI   = S + OFF_XI;
    float* E1   = S + OFF_E1;
    float* E2   = S + OFF_E2;
    float* XP   = S + OFF_XP;
    float* Rb   = S + OFF_R;
    float* PR   = S + OFF_PR;
    float* DH   = S + OFF_DH;
    float* O4   = S + OFF_O4;

    const size_t MSZ = 512 * 512;   // one 512x512 matrix
    auto Rp = [&](int nb, int t) -> float* { return Rb + ((size_t)nb * 12 + t) * MSZ; };

    stats_kernel<<<32, 256>>>(x_enc, xn, mnA, sdA);
    filter_kernel<<<4, 512>>>(maskw, Kf);

    // R_1 = whh (copy into power table)
    for (int nb = 0; nb < 4; nb++)
        cudaMemcpyAsync(Rp(nb, 1), whh + (size_t)nb * MSZ, MSZ * sizeof(float),
                        cudaMemcpyDeviceToDevice, 0);

    GemmArgs ga;
    // --- matrix powers R_t = whh^t, t = 2..11 (4 doubling launches, NN) ---
    ga.M = 512; ga.N = 512; ga.K = 512;
    for (int nb = 0; nb < 4; nb++) {
        ga.A[nb] = Rp(nb, 1); ga.Bp[nb] = Rp(nb, 1); ga.C[nb] = Rp(nb, 2);
    }
    sgemm<1, false, false><<<dim3(4, 4, 4), 256>>>(ga);

    for (int nb = 0; nb < 4; nb++)
        for (int j = 0; j < 2; j++) {
            int z = nb * 2 + j;
            ga.A[z] = Rp(nb, 2); ga.Bp[z] = Rp(nb, 1 + j); ga.C[z] = Rp(nb, 3 + j);
        }
    sgemm<1, false, false><<<dim3(4, 4, 8), 256>>>(ga);

    for (int nb = 0; nb < 4; nb++)
        for (int j = 0; j < 4; j++) {
            int z = nb * 4 + j;
            ga.A[z] = Rp(nb, 4); ga.Bp[z] = Rp(nb, 1 + j); ga.C[z] = Rp(nb, 5 + j);
        }
    sgemm<1, false, false><<<dim3(4, 4, 16), 256>>>(ga);

    for (int nb = 0; nb < 4; nb++)
        for (int j = 0; j < 3; j++) {
            int z = nb * 3 + j;
            ga.A[z] = Rp(nb, 8); ga.Bp[z] = Rp(nb, 1 + j); ga.C[z] = Rp(nb, 9 + j);
        }
    sgemm<1, false, false><<<dim3(4, 4, 12), 256>>>(ga);

    // --- Fourier filter as circular conv ---
    conv_kernel<<<dim3(256, 4), 256>>>(xn, Kf, XI);

    // --- encoder L1: relu(res @ ew1^T + b1): [2048x2048]x[1024x2048]^T ---
    ga.M = 2048; ga.N = 1024; ga.K = 2048;
    for (int nb = 0; nb < 4; nb++) {
        ga.A[nb]    = XI + (size_t)nb * (2048u * 2048u);
        ga.Bp[nb]   = ew1 + (size_t)nb * (1024u * 2048u);
        ga.bias[nb] = eb1 + (size_t)nb * 1024u;
        ga.C[nb]    = E1 + (size_t)nb * (2048u * 1024u);
    }
    sgemm<0, true, true><<<dim3(8, 16, 4), 256>>>(ga);

    // --- encoder L2: [2048x1024]x[512x1024]^T ---
    ga.M = 2048; ga.N = 512; ga.K = 1024;
    for (int nb = 0; nb < 4; nb++) {
        ga.A[nb]    = E1 + (size_t)nb * (2048u * 1024u);
        ga.Bp[nb]   = ew2 + (size_t)nb * (512u * 1024u);
        ga.bias[nb] = eb2 + (size_t)nb * 512u;
        ga.C[nb]    = E2 + (size_t)nb * (2048u * 512u);
    }
    sgemm<0, true, false><<<dim3(4, 16, 4), 256>>>(ga);

    // --- XP = E2 @ wxh^T ---
    ga.M = 2048; ga.N = 512; ga.K = 512;
    for (int nb = 0; nb < 4; nb++) {
        ga.A[nb]  = E2 + (size_t)nb * (2048u * 512u);
        ga.Bp[nb] = wxh + (size_t)nb * MSZ;
        ga.C[nb]  = XP + (size_t)nb * (2048u * 512u);
    }
    sgemm<0, false, false><<<dim3(4, 16, 4), 256>>>(ga);

    // --- RNN + free-run folded: preds = XPc[256x4096] @ gathered-R[4096x2048] ---
    ga.M = 256; ga.N = 2048; ga.K = 4096;
    for (int nb = 0; nb < 4; nb++) {
        ga.A[nb]  = XP + (size_t)nb * (2048u * 512u);   // viewed [256, 4096]
        ga.Bp[nb] = Rb + (size_t)nb * 12 * MSZ;          // R table base
        ga.C[nb]  = PR + (size_t)nb * (256u * 2048u);
    }
    sgemm<2, false, false><<<dim3(16, 2, 4), 256>>>(ga);

    // --- LayerNorm ---
    ln_kernel<<<512, 256>>>(PR, lng, lnbta);

    // --- decoder L1: relu(P @ dw1^T + b1): [1024x512]x[1024x512]^T ---
    ga.M = 1024; ga.N = 1024; ga.K = 512;
    for (int nb = 0; nb < 4; nb++) {
        ga.A[nb]    = PR + (size_t)nb * (256u * 2048u);  // [1024, 512]
        ga.Bp[nb]   = dw1 + (size_t)nb * (1024u * 512u);
        ga.bias[nb] = db1 + (size_t)nb * 1024u;
        ga.C[nb]    = DH + (size_t)nb * (1024u * 1024u);
    }
    sgemm<0, true, true><<<dim3(8, 8, 4), 256>>>(ga);

    // --- decoder L2: [1024x1024]x[2048x1024]^T ---
    ga.M = 1024; ga.N = 2048; ga.K = 1024;
    for (int nb = 0; nb < 4; nb++) {
        ga.A[nb]    = DH + (size_t)nb * (1024u * 1024u);
        ga.Bp[nb]   = dw2 + (size_t)nb * (2048u * 1024u);
        ga.bias[nb] = db2 + (size_t)nb * 2048u;
        ga.C[nb]    = O4 + (size_t)nb * (1024u * 2048u);
    }
    sgemm<0, true, false><<<dim3(16, 8, 4), 256>>>(ga);

    // --- final combine ---
    final_kernel<<<8192, 256>>>(O4, mnA, sdA, out);
}

// round 10
// speedup vs baseline: 2.1452x; 2.1399x over previous
#include <cuda_runtime.h>
#include <math.h>
#include <stdint.h>
#include <stddef.h>

#define Bn 256
#define Ln 512
#define Cn 32

// ---------------- scratch (floats), no allocations ----------------
#define OFF_XN    0u
#define OFF_MEAN  4194304u
#define OFF_STD   4202496u
#define OFF_KF    4210688u
#define OFF_XI    4212736u     // [4][2048][2048]
#define OFF_E1    20989952u    // [4][2048][1024]
#define OFF_E2    29378560u    // [4][2048][512]
#define OFF_XP    33572864u    // [4][2048][512]
#define OFF_R     37767168u    // [4][12][512*512]
#define OFF_PR    50350080u    // [4][256][2048]
#define OFF_DH    52447232u    // [4][1024][1024]
#define OFF_O4    56641536u    // [4][1024][2048]
#define OFF_S     65030144u    // [4][9][512*512]
#define SCR_TOTAL 74467328u

__device__ __align__(1024) float g_scratch[SCR_TOTAL];

__device__ __forceinline__ uint32_t smem_u32(const void* p) {
    uint32_t a;
    asm("{ .reg .u64 t; cvta.to.shared.u64 t, %1; cvt.u32.u64 %0, t; }" : "=r"(a) : "l"(p));
    return a;
}

#define LDSM4(r, a) \
    asm volatile("ldmatrix.sync.aligned.m8n8.x4.shared.b16 {%0,%1,%2,%3}, [%4];" \
        : "=r"((r)[0]), "=r"((r)[1]), "=r"((r)[2]), "=r"((r)[3]) : "r"(a))
#define LDSM2(r, a) \
    asm volatile("ldmatrix.sync.aligned.m8n8.x2.shared.b16 {%0,%1}, [%2];" \
        : "=r"((r)[0]), "=r"((r)[1]) : "r"(a))
#define MMA16816(d, a, b) \
    asm volatile("mma.sync.aligned.m16n8k16.row.col.f32.bf16.bf16.f32 " \
        "{%0,%1,%2,%3}, {%4,%5,%6,%7}, {%8,%9}, {%0,%1,%2,%3};" \
        : "+f"((d)[0]), "+f"((d)[1]), "+f"((d)[2]), "+f"((d)[3]) \
        : "r"((a)[0]), "r"((a)[1]), "r"((a)[2]), "r"((a)[3]), "r"((b)[0]), "r"((b)[1]))

// ===========================================================================
// HMMA NT GEMM: C[m,n] = sum_k A[m,k]*B[n,k], bf16 hi/lo (3 terms), fp32 acc.
// CTA 128x128, 8 warps (2x4 of 64x32), K staged 32 fp32, double-buffered smem.
// GB=1: B rows gathered from the R-power table (RNN fold).
// ===========================================================================
struct TCArgs {
    const float* A[32];
    const float* B[32];
    const float* bias[32];
    float*       C[32];
};

#define LDAe  40        // padded bf16 row stride (elements)
#define MATB  10240u    // 128 * 40 * 2 bytes, one bf16 matrix
#define BUFB  40960u    // Ah, Al, Bh, Bl
#define DYNSM 81920u    // 2 buffers

template<int GB, bool BIAS, bool RELU>
__global__ __launch_bounds__(256, 1) void tc_gemm(const TCArgs ta, int M, int N, int K)
{
    extern __shared__ char smem[];
    const uint32_t sbase = smem_u32(smem);
    const int tid = threadIdx.x, wid = tid >> 5, lane = tid & 31;
    const int z = blockIdx.z;
    const int m0 = blockIdx.y * 128, n0 = blockIdx.x * 128;
    const float* __restrict__ Ab = ta.A[z];
    const float* __restrict__ Bb = ta.B[z];
    const int S = K >> 5;
    const int wm = (wid & 1) * 64;
    const int wn = (wid >> 1) * 32;
    const int lrow = tid >> 3;        // 0..31
    const int col4 = tid & 7;         // float4 column within 32-wide stage

    float acc[4][4][4];
#pragma unroll
    for (int i = 0; i < 4; i++)
#pragma unroll
        for (int j = 0; j < 4; j++)
#pragma unroll
            for (int q = 0; q < 4; q++) acc[i][j][q] = 0.f;

    float4 ar[4], br[4];
    auto loadA = [&](int k0) {
#pragma unroll
        for (int q = 0; q < 4; q++)
            ar[q] = *(const float4*)(Ab + (size_t)(m0 + lrow + 32 * q) * K + k0 + col4 * 4);
    };
    auto loadB = [&](int k0) {
#pragma unroll
        for (int q = 0; q < 4; q++) {
            const int row = lrow + 32 * q;
            const float* src;
            if (GB == 0) {
                src = Bb + (size_t)(n0 + row) * K + k0 + col4 * 4;
            } else {
                const int n = n0 + row;
                src = Bb + ((size_t)(8 + (n >> 9) - (k0 >> 9)) << 18)
                         + ((size_t)(n & 511) << 9) + (k0 & 511) + col4 * 4;
            }
            br[q] = *(const float4*)src;
        }
    };
    auto cvst = [&](uint32_t hioff, int row, float4 v) {
        uint32_t h0, h1, l0, l1;
        asm("cvt.rn.bf16x2.f32 %0, %1, %2;" : "=r"(h0) : "f"(v.y), "f"(v.x));
        asm("cvt.rn.bf16x2.f32 %0, %1, %2;" : "=r"(h1) : "f"(v.w), "f"(v.z));
        float hx = __uint_as_float(h0 << 16);
        float hy = __uint_as_float(h0 & 0xFFFF0000u);
        float hz = __uint_as_float(h1 << 16);
        float hw = __uint_as_float(h1 & 0xFFFF0000u);
        asm("cvt.rn.bf16x2.f32 %0, %1, %2;" : "=r"(l0) : "f"(v.y - hy), "f"(v.x - hx));
        asm("cvt.rn.bf16x2.f32 %0, %1, %2;" : "=r"(l1) : "f"(v.w - hw), "f"(v.z - hz));
        char* p = smem + hioff + row * (LDAe * 2) + col4 * 8;
        *(uint2*)p = make_uint2(h0, h1);
        *(uint2*)(p + MATB) = make_uint2(l0, l1);
    };

    loadA(0); loadB(0);
    for (int s = 0; s < S; s++) {
        const uint32_t bo = (uint32_t)(s & 1) * BUFB;
#pragma unroll
        for (int q = 0; q < 4; q++) cvst(bo, lrow + 32 * q, ar[q]);
#pragma unroll
        for (int q = 0; q < 4; q++) cvst(bo + 2u * MATB, lrow + 32 * q, br[q]);
        __syncthreads();
        if (s + 1 < S) { loadA((s + 1) * 32); loadB((s + 1) * 32); }

        const uint32_t sA = sbase + bo;
        const uint32_t sB = sA + 2u * MATB;
#pragma unroll
        for (int kk = 0; kk < 32; kk += 16) {
            uint32_t ah[4][4], al[4][4], bh[4][2], bl[4][2];
#pragma unroll
            for (int i = 0; i < 4; i++) {
                uint32_t a = sA + (uint32_t)((wm + 16 * i + (lane & 15)) * (LDAe * 2)
                                             + (kk + ((lane >> 4) << 3)) * 2);
                LDSM4(ah[i], a);
                LDSM4(al[i], a + MATB);
            }
#pragma unroll
            for (int j = 0; j < 4; j++) {
                uint32_t a = sB + (uint32_t)((wn + 8 * j + (lane & 7)) * (LDAe * 2)
                                             + (kk + (((lane >> 3) & 1) << 3)) * 2);
                LDSM2(bh[j], a);
                LDSM2(bl[j], a + MATB);
            }
#pragma unroll
            for (int i = 0; i < 4; i++)
#pragma unroll
                for (int j = 0; j < 4; j++) {
                    MMA16816(acc[i][j], ah[i], bh[j]);
                    MMA16816(acc[i][j], ah[i], bl[j]);
                    MMA16816(acc[i][j], al[i], bh[j]);
                }
        }
        // next store is separated from this compute by the next iteration's sync
        if (s + 1 < S) continue;
    }

    const float* bb = BIAS ? ta.bias[z] : (const float*)0;
    float* C = ta.C[z];
#pragma unroll
    for (int i = 0; i < 4; i++) {
        const int m = m0 + wm + 16 * i + (lane >> 2);
#pragma unroll
        for (int j = 0; j < 4; j++) {
            const int n = n0 + wn + 8 * j + (lane & 3) * 2;
            float2 v0 = make_float2(acc[i][j][0], acc[i][j][1]);
            float2 v1 = make_float2(acc[i][j][2], acc[i][j][3]);
            if (BIAS) {
                float2 b2 = *(const float2*)(bb + n);
                v0.x += b2.x; v0.y += b2.y; v1.x += b2.x; v1.y += b2.y;
            }
            if (RELU) {
                v0.x = fmaxf(v0.x, 0.f); v0.y = fmaxf(v0.y, 0.f);
                v1.x = fmaxf(v1.x, 0.f); v1.y = fmaxf(v1.y, 0.f);
            }
            *(float2*)(C + (size_t)m * N + n) = v0;
            *(float2*)(C + (size_t)(m + 8) * N + n) = v1;
        }
    }
}

// ---------------- stats / filter / conv / transpose / ln / final ----------
__global__ __launch_bounds__(256) void stats_kernel(
    const float* __restrict__ x, float* __restrict__ xn,
    float* __restrict__ meanA, float* __restrict__ stdA)
{
    int g = blockIdx.x * 256 + threadIdx.x;
    int b = g >> 5, c = g & 31;
    const float* p = x + (size_t)b * (Ln * Cn) + c;
    float s = 0.f, sq = 0.f;
    for (int l = 0; l < Ln; l++) { float v = p[l * Cn]; s += v; sq = fmaf(v, v, sq); }
    float mu = s * (1.f / Ln);
    float sd = sqrtf(sq * (1.f / Ln) - mu * mu + 1e-5f);
    meanA[g] = mu; stdA[g] = sd;
    float inv = 1.f / sd;
    float* q = xn + (size_t)b * (Ln * Cn) + c;
    for (int l = 0; l < Ln; l++) q[l * Cn] = (p[l * Cn] - mu) * inv;
}

__global__ __launch_bounds__(512) void filter_kernel(
    const float* __restrict__ mw, float* __restrict__ Kf)
{
    int nb = blockIdx.x, t = threadIdx.x;
    const float* m = mw + nb * 257;
    float s0 = 1.f / (1.f + expf(-m[0]));
    float s256 = 1.f / (1.f + expf(-m[256]));
    float acc = s0 + ((t & 1) ? -s256 : s256);
    const float step = 6.283185307179586f / 512.f;
    for (int f = 1; f < 256; f++) {
        float sf = 1.f / (1.f + expf(-m[f]));
        acc = fmaf(2.f * sf, cosf(step * (float)((f * t) & 511)), acc);
    }
    Kf[nb * 512 + t] = acc * (1.f / 512.f);
}

__global__ __launch_bounds__(256) void conv_kernel(
    const float* __restrict__ xn, const float* __restrict__ Kf, float* __restrict__ xi)
{
    __shared__ float xs[256 * Cn];
    __shared__ float ks[1024];
    const int b = blockIdx.x, nb = blockIdx.y, tid = threadIdx.x;
    for (int i = tid; i < 1024; i += 256) ks[i] = Kf[nb * 512 + (i & 511)];
    const int l0 = tid, l1 = tid + 256;
    float acc0[32], acc1[32];
#pragma unroll
    for (int j = 0; j < 32; j++) { acc0[j] = 0.f; acc1[j] = 0.f; }
    for (int ch = 0; ch < 2; ch++) {
        __syncthreads();
        const float4* src = (const float4*)(xn + (size_t)b * (Ln * Cn) + ch * (256 * Cn));
        for (int i = tid; i < 2048; i += 256) ((float4*)xs)[i] = src[i];
        __syncthreads();
        const int base = ch * 256;
        for (int lp = 0; lp < 256; lp++) {
            const int lg = base + lp;
            const float k0 = ks[l0 - lg + 512];
            const float k1 = ks[l1 - lg + 512];
            const float4* row = (const float4*)(xs + lp * Cn);
#pragma unroll
            for (int j = 0; j < 8; j++) {
                float4 xv = row[j];
                acc0[j*4+0] = fmaf(k0, xv.x, acc0[j*4+0]); acc0[j*4+1] = fmaf(k0, xv.y, acc0[j*4+1]);
                acc0[j*4+2] = fmaf(k0, xv.z, acc0[j*4+2]); acc0[j*4+3] = fmaf(k0, xv.w, acc0[j*4+3]);
                acc1[j*4+0] = fmaf(k1, xv.x, acc1[j*4+0]); acc1[j*4+1] = fmaf(k1, xv.y, acc1[j*4+1]);
                acc1[j*4+2] = fmaf(k1, xv.z, acc1[j*4+2]); acc1[j*4+3] = fmaf(k1, xv.w, acc1[j*4+3]);
            }
        }
    }
    float* o = xi + (size_t)nb * (Bn * Ln * Cn) + (size_t)b * (Ln * Cn);
#pragma unroll
    for (int j = 0; j < 8; j++) {
        ((float4*)(o + l0 * Cn))[j] = make_float4(acc0[j*4], acc0[j*4+1], acc0[j*4+2], acc0[j*4+3]);
        ((float4*)(o + l1 * Cn))[j] = make_float4(acc1[j*4], acc1[j*4+1], acc1[j*4+2], acc1[j*4+3]);
    }
}

__global__ __launch_bounds__(256) void transpose512(
    const float* __restrict__ in, float* __restrict__ out)
{
    __shared__ float t[32][33];
    const int x0 = blockIdx.x * 32, y0 = blockIdx.y * 32;
    const int tx = threadIdx.x & 31, ty = threadIdx.x >> 5;
#pragma unroll
    for (int j = 0; j < 32; j += 8) t[ty + j][tx] = in[(y0 + ty + j) * 512 + x0 + tx];
    __syncthreads();
#pragma unroll
    for (int j = 0; j < 32; j += 8) out[(x0 + ty + j) * 512 + y0 + tx] = t[tx][ty + j];
}

__global__ __launch_bounds__(256) void ln_kernel(
    float* __restrict__ Pr, const float* __restrict__ g, const float* __restrict__ bta)
{
    const int warp = threadIdx.x >> 5, lane = threadIdx.x & 31;
    const int row = blockIdx.x * 8 + warp;
    const int nb = row >> 10;
    float* p = Pr + (size_t)row * 512;
    float v[16], s = 0.f, sq = 0.f;
#pragma unroll
    for (int i = 0; i < 16; i++) { v[i] = p[lane + 32 * i]; s += v[i]; sq = fmaf(v[i], v[i], sq); }
#pragma unroll
    for (int off = 16; off > 0; off >>= 1) {
        s += __shfl_xor_sync(0xFFFFFFFFu, s, off);
        sq += __shfl_xor_sync(0xFFFFFFFFu, sq, off);
    }
    float mu = s * (1.f / 512.f);
    float r = rsqrtf(sq * (1.f / 512.f) - mu * mu + 1e-5f);
    const float* gg = g + nb * 512;
    const float* bb = bta + nb * 512;
#pragma unroll
    for (int i = 0; i < 16; i++) {
        int d = lane + 32 * i;
        p[d] = fmaf((v[i] - mu) * r, gg[d], bb[d]);
    }
}

__global__ __launch_bounds__(256) void final_kernel(
    const float* __restrict__ O4, const float* __restrict__ meanA,
    const float* __restrict__ stdA, float* __restrict__ out)
{
    int idx = blockIdx.x * 256 + threadIdx.x;
    int b = idx >> 13, c = idx & 31;
    size_t m = (size_t)((b * 4) + ((idx >> 11) & 3)) * 2048 + (idx & 2047);
    const size_t str = (size_t)1024 * 2048;
    float v = O4[m] + O4[m + str] + O4[m + 2 * str] + O4[m + 3 * str];
    int bc = b * 32 + c;
    out[idx] = fmaf(v, stdA[bc], meanA[bc]);
}

// ---------------- launcher ----------------
extern "C" void kernel_launch(void* const* d_in, const int* in_sizes, int n_in,
                              void* d_out, int out_size)
{
    (void)in_sizes; (void)n_in; (void)out_size;
    const float* x_enc = (const float*)d_in[0];
    const float* maskw = (const float*)d_in[4];
    const float* ew1 = (const float*)d_in[5];
    const float* eb1 = (const float*)d_in[6];
    const float* ew2 = (const float*)d_in[7];
    const float* eb2 = (const float*)d_in[8];
    const float* wxh = (const float*)d_in[9];
    const float* whh = (const float*)d_in[10];
    const float* lng = (const float*)d_in[11];
    const float* lnb = (const float*)d_in[12];
    const float* dw1 = (const float*)d_in[13];
    const float* db1 = (const float*)d_in[14];
    const float* dw2 = (const float*)d_in[15];
    const float* db2 = (const float*)d_in[16];
    float* out = (float*)d_out;

    float* S = nullptr;
    cudaGetSymbolAddress((void**)&S, g_scratch);
    float* xn = S + OFF_XN;  float* mnA = S + OFF_MEAN; float* sdA = S + OFF_STD;
    float* Kf = S + OFF_KF;  float* XI = S + OFF_XI;   float* E1 = S + OFF_E1;
    float* E2 = S + OFF_E2;  float* XP = S + OFF_XP;   float* Rb = S + OFF_R;
    float* PR = S + OFF_PR;  float* DH = S + OFF_DH;   float* O4 = S + OFF_O4;
    float* Sb = S + OFF_S;

    cudaFuncSetAttribute(tc_gemm<0,false,false>, cudaFuncAttributeMaxDynamicSharedMemorySize, DYNSM);
    cudaFuncSetAttribute(tc_gemm<0,true,true>,   cudaFuncAttributeMaxDynamicSharedMemorySize, DYNSM);
    cudaFuncSetAttribute(tc_gemm<0,true,false>,  cudaFuncAttributeMaxDynamicSharedMemorySize, DYNSM);
    cudaFuncSetAttribute(tc_gemm<1,false,false>, cudaFuncAttributeMaxDynamicSharedMemorySize, DYNSM);

    const size_t MSZ = 512 * 512;
    auto Rp = [&](int nb, int t) -> float* { return Rb + ((size_t)nb * 12 + t) * MSZ; };
    auto Sp = [&](int nb, int t) -> float* { return Sb + ((size_t)nb * 9 + t) * MSZ; };

    stats_kernel<<<32, 256>>>(x_enc, xn, mnA, sdA);
    filter_kernel<<<4, 512>>>(maskw, Kf);

    for (int nb = 0; nb < 4; nb++)
        cudaMemcpyAsync(Rp(nb, 1), whh + (size_t)nb * MSZ, MSZ * sizeof(float),
                        cudaMemcpyDeviceToDevice, 0);
    for (int nb = 0; nb < 4; nb++)
        transpose512<<<dim3(16, 16, 1), 256>>>(whh + (size_t)nb * MSZ, Sp(nb, 1));

    TCArgs ga;
    // round 1: R2 = R1*R1 (A=R1,B=S1), S2 = S1*S1 (A=S1,B=R1)
    for (int nb = 0; nb < 4; nb++) {
        ga.A[nb*2+0] = Rp(nb,1); ga.B[nb*2+0] = Sp(nb,1); ga.C[nb*2+0] = Rp(nb,2);
        ga.A[nb*2+1] = Sp(nb,1); ga.B[nb*2+1] = Rp(nb,1); ga.C[nb*2+1] = Sp(nb,2);
    }
    tc_gemm<0,false,false><<<dim3(4,4,8), 256, DYNSM>>>(ga, 512, 512, 512);

    // round 2: R3 (A=R2,B=S1), R4 (A=R2,B=S2), S3 (A=S1,B=R2), S4 (A=S2,B=R2)
    for (int nb = 0; nb < 4; nb++) {
        int z = nb * 4;
        ga.A[z+0] = Rp(nb,2); ga.B[z+0] = Sp(nb,1); ga.C[z+0] = Rp(nb,3);
        ga.A[z+1] = Rp(nb,2); ga.B[z+1] = Sp(nb,2); ga.C[z+1] = Rp(nb,4);
        ga.A[z+2] = Sp(nb,1); ga.B[z+2] = Rp(nb,2); ga.C[z+2] = Sp(nb,3);
        ga.A[z+3] = Sp(nb,2); ga.B[z+3] = Rp(nb,2); ga.C[z+3] = Sp(nb,4);
    }
    tc_gemm<0,false,false><<<dim3(4,4,16), 256, DYNSM>>>(ga, 512, 512, 512);

    // round 3: R5..R8 (A=R4,B=Sj), S5..S8 (A=Sj,B=R4), j=1..4
    for (int nb = 0; nb < 4; nb++)
        for (int j = 1; j <= 4; j++) {
            int z = nb * 8 + (j - 1);
            ga.A[z] = Rp(nb,4); ga.B[z] = Sp(nb,j); ga.C[z] = Rp(nb,4+j);
            int z2 = nb * 8 + 4 + (j - 1);
            ga.A[z2] = Sp(nb,j); ga.B[z2] = Rp(nb,4); ga.C[z2] = Sp(nb,4+j);
        }
    tc_gemm<0,false,false><<<dim3(4,4,32), 256, DYNSM>>>(ga, 512, 512, 512);

    // round 4: R9..R11 (A=R8, B=Sj), j=1..3
    for (int nb = 0; nb < 4; nb++)
        for (int j = 1; j <= 3; j++) {
            int z = nb * 3 + (j - 1);
            ga.A[z] = Rp(nb,8); ga.B[z] = Sp(nb,j); ga.C[z] = Rp(nb,8+j);
        }
    tc_gemm<0,false,false><<<dim3(4,4,12), 256, DYNSM>>>(ga, 512, 512, 512);

    conv_kernel<<<dim3(256, 4), 256>>>(xn, Kf, XI);

    // enc1: relu(XI @ ew1^T + b1)  [2048x2048]x[1024x2048]^T
    for (int nb = 0; nb < 4; nb++) {
        ga.A[nb] = XI + (size_t)nb * (2048u * 2048u);
        ga.B[nb] = ew1 + (size_t)nb * (1024u * 2048u);
        ga.bias[nb] = eb1 + (size_t)nb * 1024u;
        ga.C[nb] = E1 + (size_t)nb * (2048u * 1024u);
    }
    tc_gemm<0,true,true><<<dim3(8,16,4), 256, DYNSM>>>(ga, 2048, 1024, 2048);

    // enc2
    for (int nb = 0; nb < 4; nb++) {
        ga.A[nb] = E1 + (size_t)nb * (2048u * 1024u);
        ga.B[nb] = ew2 + (size_t)nb * (512u * 1024u);
        ga.bias[nb] = eb2 + (size_t)nb * 512u;
        ga.C[nb] = E2 + (size_t)nb * (2048u * 512u);
    }
    tc_gemm<0,true,false><<<dim3(4,16,4), 256, DYNSM>>>(ga, 2048, 512, 1024);

    // XP = E2 @ wxh^T
    for (int nb = 0; nb < 4; nb++) {
        ga.A[nb] = E2 + (size_t)nb * (2048u * 512u);
        ga.B[nb] = wxh + (size_t)nb * MSZ;
        ga.C[nb] = XP + (size_t)nb * (2048u * 512u);
    }
    tc_gemm<0,false,false><<<dim3(4,16,4), 256, DYNSM>>>(ga, 2048, 512, 512);

    // RNN fold: PR[256x2048] = XP[256x4096] @ gathered-R[2048x4096]^T
    for (int nb = 0; nb < 4; nb++) {
        ga.A[nb] = XP + (size_t)nb * (2048u * 512u);
        ga.B[nb] = Rb + (size_t)nb * 12 * MSZ;
        ga.C[nb] = PR + (size_t)nb * (256u * 2048u);
    }
    tc_gemm<1,false,false><<<dim3(16,2,4), 256, DYNSM>>>(ga, 256, 2048, 4096);

    ln_kernel<<<512, 256>>>(PR, lng, lnb);

    // dec1: relu(PR @ dw1^T + b1)
    for (int nb = 0; nb < 4; nb++) {
        ga.A[nb] = PR + (size_t)nb * (256u * 2048u);
        ga.B[nb] = dw1 + (size_t)nb * (1024u * 512u);
        ga.bias[nb] = db1 + (size_t)nb * 1024u;
        ga.C[nb] = DH + (size_t)nb * (1024u * 1024u);
    }
    tc_gemm<0,true,true><<<dim3(8,8,4), 256, DYNSM>>>(ga, 1024, 1024, 512);

    // dec2
    for (int nb = 0; nb < 4; nb++) {
        ga.A[nb] = DH + (size_t)nb * (1024u * 1024u);
        ga.B[nb] = dw2 + (size_t)nb * (2048u * 1024u);
        ga.bias[nb] = db2 + (size_t)nb * 2048u;
        ga.C[nb] = O4 + (size_t)nb * (1024u * 2048u);
    }
    tc_gemm<0,true,false><<<dim3(16,8,4), 256, DYNSM>>>(ga, 1024, 2048, 1024);

    final_kernel<<<8192, 256>>>(O4, mnA, sdA, out);
}

// round 12
// speedup vs baseline: 2.4701x; 1.1514x over previous
#include <cuda_runtime.h>
#include <math.h>
#include <stdint.h>
#include <stddef.h>

#define Bn 256
#define Ln 512
#define Cn 32

// ---------------- scratch (floats), no allocations ----------------
#define OFF_XN    0u           // xn_bcl [8192][512]
#define OFF_MEAN  4194304u
#define OFF_STD   4202496u
#define OFF_KF    4210688u
#define OFF_XI    4212736u     // [4][2048][2048]  (enc1 layout)
#define OFF_E1    20989952u    // [4][2048][1024]
#define OFF_E2    29378560u    // [4][2048][512]
#define OFF_XP    33572864u    // [4][2048][512]
#define OFF_R     37767168u    // [4][12][512*512]
#define OFF_PR    50350080u    // [4][256*2048]
#define OFF_DH    52447232u    // [4][1024][1024]
#define OFF_S     65030144u    // [4][9][512*512]
#define SCR_TOTAL 74467328u

__device__ __align__(1024) float g_scratch[SCR_TOTAL];

__device__ __forceinline__ uint32_t smem_u32(const void* p) {
    uint32_t a;
    asm("{ .reg .u64 t; cvta.to.shared.u64 t, %1; cvt.u32.u64 %0, t; }" : "=r"(a) : "l"(p));
    return a;
}

#define LDSM4(r, a) \
    asm volatile("ldmatrix.sync.aligned.m8n8.x4.shared.b16 {%0,%1,%2,%3}, [%4];" \
        : "=r"((r)[0]), "=r"((r)[1]), "=r"((r)[2]), "=r"((r)[3]) : "r"(a))
#define LDSM2(r, a) \
    asm volatile("ldmatrix.sync.aligned.m8n8.x2.shared.b16 {%0,%1}, [%2];" \
        : "=r"((r)[0]), "=r"((r)[1]) : "r"(a))
#define MMA16816(d, a, b) \
    asm volatile("mma.sync.aligned.m16n8k16.row.col.f32.bf16.bf16.f32 " \
        "{%0,%1,%2,%3}, {%4,%5,%6,%7}, {%8,%9}, {%0,%1,%2,%3};" \
        : "+f"((d)[0]), "+f"((d)[1]), "+f"((d)[2]), "+f"((d)[3]) \
        : "r"((a)[0]), "r"((a)[1]), "r"((a)[2]), "r"((a)[3]), "r"((b)[0]), "r"((b)[1]))

// ===========================================================================
// HMMA NT GEMM: C[m,n] = sum_k A[m,k]*B[n,k], bf16 hi/lo (3 terms), fp32 acc.
// CTA 128x128, 8 warps (2x4 of 64x32), K staged 32 fp32, double-buffered smem.
// AG: 0 = row-major A; 1 = dec2 A gather over [4][1024][1024].
// GB: 0 = row-major B[n,k]; 1 = RNN R-table gather; 2 = circular-conv tap
//     gather B[n,k] = tap[(n-k)&511]; 3 = dec2 B gather over [4][2048][1024].
// EPI: 0 = normal (BIAS/RELU);
//      1 = conv scatter: smem-transposed store into XI enc1 layout;
//      2 = dec2-final: 4-way bias sum + (v*std+mean) with (b,s,p,c) remap.
// ===========================================================================
struct TCArgs {
    const float* A[32];
    const float* B[32];
    const float* bias[32];
    float*       C[32];
    const float* mean;
    const float* stdv;
};

#define LDAe  40        // padded bf16 row stride (elements)
#define MATB  10240u    // 128 * 40 * 2 bytes, one bf16 matrix
#define BUFB  40960u    // Ah, Al, Bh, Bl
#define DYNSM 81920u    // 2 buffers (conv epilogue fp32 tile 128*129*4 fits)

template<int AG, int GB, int EPI, bool BIAS, bool RELU>
__global__ __launch_bounds__(256, 1) void tc_gemm(const TCArgs ta, int M, int N, int K)
{
    extern __shared__ char smem[];
    const uint32_t sbase = smem_u32(smem);
    const int tid = threadIdx.x, wid = tid >> 5, lane = tid & 31;
    const int z = blockIdx.z;
    const int m0 = blockIdx.y * 128, n0 = blockIdx.x * 128;
    const float* __restrict__ Ab = ta.A[z];
    const float* __restrict__ Bb = ta.B[z];
    const int S = K >> 5;
    const int wm = (wid & 1) * 64;
    const int wn = (wid >> 1) * 32;
    const int lrow = tid >> 3;        // 0..31
    const int col4 = tid & 7;         // float4 column within 32-wide stage

    float acc[4][4][4];
#pragma unroll
    for (int i = 0; i < 4; i++)
#pragma unroll
        for (int j = 0; j < 4; j++)
#pragma unroll
            for (int q = 0; q < 4; q++) acc[i][j][q] = 0.f;

    float4 ar[4], br[4];
    auto loadA = [&](int k0) {
#pragma unroll
        for (int q = 0; q < 4; q++) {
            const int row = m0 + lrow + 32 * q;
            const int kk = k0 + col4 * 4;
            const float* src;
            if (AG == 0) {
                src = Ab + (size_t)row * K + kk;
            } else {  // dec2: A[m, nb*1024+k] = DH[nb][m][k]
                src = Ab + ((size_t)(kk >> 10) << 20) + (size_t)row * 1024 + (kk & 1023);
            }
            ar[q] = *(const float4*)src;
        }
    };
    auto loadB = [&](int k0) {
#pragma unroll
        for (int q = 0; q < 4; q++) {
            const int row = lrow + 32 * q;
            const int n = n0 + row;
            const int kk = k0 + col4 * 4;
            if (GB == 0) {
                br[q] = *(const float4*)(Bb + (size_t)n * K + kk);
            } else if (GB == 1) {
                const float* src = Bb + ((size_t)(8 + (n >> 9) - (kk >> 9)) << 18)
                                      + ((size_t)(n & 511) << 9) + (kk & 511);
                br[q] = *(const float4*)src;
            } else if (GB == 2) {
                br[q].x = Bb[(n - kk) & 511];
                br[q].y = Bb[(n - kk - 1) & 511];
                br[q].z = Bb[(n - kk - 2) & 511];
                br[q].w = Bb[(n - kk - 3) & 511];
            } else {  // dec2: B[n, nb*1024+k] = dw2[nb][n][k]
                const float* src = Bb + (size_t)(kk >> 10) * (2048u * 1024u)
                                      + (size_t)n * 1024 + (kk & 1023);
                br[q] = *(const float4*)src;
            }
        }
    };
    auto cvst = [&](uint32_t hioff, int row, float4 v) {
        uint32_t h0, h1, l0, l1;
        asm("cvt.rn.bf16x2.f32 %0, %1, %2;" : "=r"(h0) : "f"(v.y), "f"(v.x));
        asm("cvt.rn.bf16x2.f32 %0, %1, %2;" : "=r"(h1) : "f"(v.w), "f"(v.z));
        float hx = __uint_as_float(h0 << 16);
        float hy = __uint_as_float(h0 & 0xFFFF0000u);
        float hz = __uint_as_float(h1 << 16);
        float hw = __uint_as_float(h1 & 0xFFFF0000u);
        asm("cvt.rn.bf16x2.f32 %0, %1, %2;" : "=r"(l0) : "f"(v.y - hy), "f"(v.x - hx));
        asm("cvt.rn.bf16x2.f32 %0, %1, %2;" : "=r"(l1) : "f"(v.w - hw), "f"(v.z - hz));
        char* p = smem + hioff + row * (LDAe * 2) + col4 * 8;
        *(uint2*)p = make_uint2(h0, h1);
        *(uint2*)(p + MATB) = make_uint2(l0, l1);
    };

    loadA(0); loadB(0);
    for (int s = 0; s < S; s++) {
        const uint32_t bo = (uint32_t)(s & 1) * BUFB;
#pragma unroll
        for (int q = 0; q < 4; q++) cvst(bo, lrow + 32 * q, ar[q]);
#pragma unroll
        for (int q = 0; q < 4; q++) cvst(bo + 2u * MATB, lrow + 32 * q, br[q]);
        __syncthreads();
        if (s + 1 < S) { loadA((s + 1) * 32); loadB((s + 1) * 32); }

        const uint32_t sA = sbase + bo;
        const uint32_t sB = sA + 2u * MATB;
#pragma unroll
        for (int kk = 0; kk < 32; kk += 16) {
            uint32_t ah[4][4], al[4][4], bh[4][2], bl[4][2];
#pragma unroll
            for (int i = 0; i < 4; i++) {
                uint32_t a = sA + (uint32_t)((wm + 16 * i + (lane & 15)) * (LDAe * 2)
                                             + (kk + ((lane >> 4) << 3)) * 2);
                LDSM4(ah[i], a);
                LDSM4(al[i], a + MATB);
            }
#pragma unroll
            for (int j = 0; j < 4; j++) {
                uint32_t a = sB + (uint32_t)((wn + 8 * j + (lane & 7)) * (LDAe * 2)
                                             + (kk + (((lane >> 3) & 1) << 3)) * 2);
                LDSM2(bh[j], a);
                LDSM2(bl[j], a + MATB);
            }
#pragma unroll
            for (int i = 0; i < 4; i++)
#pragma unroll
                for (int j = 0; j < 4; j++) {
                    MMA16816(acc[i][j], ah[i], bh[j]);
                    MMA16816(acc[i][j], ah[i], bl[j]);
                    MMA16816(acc[i][j], al[i], bh[j]);
                }
        }
    }

    if (EPI == 0) {
        const float* bb = BIAS ? ta.bias[z] : (const float*)0;
        float* C = ta.C[z];
#pragma unroll
        for (int i = 0; i < 4; i++) {
            const int m = m0 + wm + 16 * i + (lane >> 2);
#pragma unroll
            for (int j = 0; j < 4; j++) {
                const int n = n0 + wn + 8 * j + (lane & 3) * 2;
                float2 v0 = make_float2(acc[i][j][0], acc[i][j][1]);
                float2 v1 = make_float2(acc[i][j][2], acc[i][j][3]);
                if (BIAS) {
                    float2 b2 = *(const float2*)(bb + n);
                    v0.x += b2.x; v0.y += b2.y; v1.x += b2.x; v1.y += b2.y;
                }
                if (RELU) {
                    v0.x = fmaxf(v0.x, 0.f); v0.y = fmaxf(v0.y, 0.f);
                    v1.x = fmaxf(v1.x, 0.f); v1.y = fmaxf(v1.y, 0.f);
                }
                *(float2*)(C + (size_t)m * N + n) = v0;
                *(float2*)(C + (size_t)(m + 8) * N + n) = v1;
            }
        }
    } else if (EPI == 1) {
        // stage fp32 C tile in smem [128][129], then write XI in enc1 layout.
        __syncthreads();                       // all LDSM of last stage done
        float* T = (float*)smem;
#pragma unroll
        for (int i = 0; i < 4; i++) {
            const int mi = wm + 16 * i + (lane >> 2);
#pragma unroll
            for (int j = 0; j < 4; j++) {
                const int nj = wn + 8 * j + (lane & 3) * 2;
                T[mi * 129 + nj]       = acc[i][j][0];
                T[mi * 129 + nj + 1]   = acc[i][j][1];
                T[(mi + 8) * 129 + nj]     = acc[i][j][2];
                T[(mi + 8) * 129 + nj + 1] = acc[i][j][3];
            }
        }
        __syncthreads();
        // tile -> XI rows (b,f): b in [b0,b0+4), f in [f0,f0+2)
        const int b0 = blockIdx.y * 4, f0 = blockIdx.x * 2;
        const int rr = tid >> 5;               // 0..7 local XI row
        const int bloc = rr >> 1, floc = rr & 1;
        float* xrow = ta.C[z] + (size_t)((b0 + bloc) * 8 + f0 + floc) * 2048;
#pragma unroll
        for (int jj = 0; jj < 16; jj++) {
            const int j4 = jj * 32 + lane;     // float4 index within 2048 row
            const int j = j4 * 4;              // = p*32 + c
            const int p = j >> 5, c = j & 31;
            float4 v;
            v.x = T[(bloc * 32 + c)     * 129 + floc * 64 + p];
            v.y = T[(bloc * 32 + c + 1) * 129 + floc * 64 + p];
            v.z = T[(bloc * 32 + c + 2) * 129 + floc * 64 + p];
            v.w = T[(bloc * 32 + c + 3) * 129 + floc * 64 + p];
            *(float4*)(xrow + j) = v;
        }
    } else {
        // dec2-final: bias = sum_nb db2[nb][n]; out = v*std[b,c] + mean[b,c]
        const float* bb = ta.bias[0];
        float* out = ta.C[0];
#pragma unroll
        for (int i = 0; i < 4; i++) {
            const int m = m0 + wm + 16 * i + (lane >> 2);
#pragma unroll
            for (int j = 0; j < 4; j++) {
                const int n = n0 + wn + 8 * j + (lane & 3) * 2;
                float b0s = bb[n]     + bb[2048 + n]     + bb[4096 + n]     + bb[6144 + n];
                float b1s = bb[n + 1] + bb[2048 + n + 1] + bb[4096 + n + 1] + bb[6144 + n + 1];
                {
                    const int b = m >> 2, c = n & 31;
                    const float sd = ta.stdv[b * 32 + c],  mu = ta.mean[b * 32 + c];
                    const float sd1 = ta.stdv[b * 32 + ((n + 1) & 31)], mu1 = ta.mean[b * 32 + ((n + 1) & 31)];
                    float2 v0 = make_float2(fmaf(acc[i][j][0] + b0s, sd, mu),
                                            fmaf(acc[i][j][1] + b1s, sd1, mu1));
                    *(float2*)(out + (size_t)b * 8192 + (m & 3) * 2048 + n) = v0;
                }
                {
                    const int m8 = m + 8;
                    const int b = m8 >> 2, c = n & 31;
                    const float sd = ta.stdv[b * 32 + c],  mu = ta.mean[b * 32 + c];
                    const float sd1 = ta.stdv[b * 32 + ((n + 1) & 31)], mu1 = ta.mean[b * 32 + ((n + 1) & 31)];
                    float2 v1 = make_float2(fmaf(acc[i][j][2] + b0s, sd, mu),
                                            fmaf(acc[i][j][3] + b1s, sd1, mu1));
                    *(float2*)(out + (size_t)b * 8192 + (m8 & 3) * 2048 + n) = v1;
                }
            }
        }
    }
}

// ---------------- stats (writes xn as [bc][l]) -----------------------------
__global__ __launch_bounds__(256) void stats_kernel(
    const float* __restrict__ x, float* __restrict__ xn_bcl,
    float* __restrict__ meanA, float* __restrict__ stdA)
{
    int g = blockIdx.x * 256 + threadIdx.x;      // b*32 + c
    int b = g >> 5, c = g & 31;
    const float* p = x + (size_t)b * (Ln * Cn) + c;
    float s = 0.f, sq = 0.f;
    for (int l = 0; l < Ln; l++) { float v = p[l * Cn]; s += v; sq = fmaf(v, v, sq); }
    float mu = s * (1.f / Ln);
    float sd = sqrtf(sq * (1.f / Ln) - mu * mu + 1e-5f);
    meanA[g] = mu; stdA[g] = sd;
    float inv = 1.f / sd;
    float* q = xn_bcl + (size_t)g * Ln;
    for (int l = 0; l < Ln; l++) q[l] = (p[l * Cn] - mu) * inv;
}

__global__ __launch_bounds__(512) void filter_kernel(
    const float* __restrict__ mw, float* __restrict__ Kf)
{
    int nb = blockIdx.x, t = threadIdx.x;
    const float* m = mw + nb * 257;
    float s0 = 1.f / (1.f + expf(-m[0]));
    float s256 = 1.f / (1.f + expf(-m[256]));
    float acc = s0 + ((t & 1) ? -s256 : s256);
    const float step = 6.283185307179586f / 512.f;
    for (int f = 1; f < 256; f++) {
        float sf = 1.f / (1.f + expf(-m[f]));
        acc = fmaf(2.f * sf, cosf(step * (float)((f * t) & 511)), acc);
    }
    Kf[nb * 512 + t] = acc * (1.f / 512.f);
}

// copy whh -> R1 and whh^T -> S1 in one launch (z = nb)
__global__ __launch_bounds__(256) void prep_R(
    const float* __restrict__ whh, float* __restrict__ Rb, float* __restrict__ Sb)
{
    __shared__ float t[32][33];
    const int nb = blockIdx.z;
    const float* in = whh + (size_t)nb * 262144;
    float* rd = Rb + ((size_t)nb * 12 + 1) * 262144;
    float* sd = Sb + ((size_t)nb * 9 + 1) * 262144;
    const int x0 = blockIdx.x * 32, y0 = blockIdx.y * 32;
    const int tx = threadIdx.x & 31, ty = threadIdx.x >> 5;
#pragma unroll
    for (int j = 0; j < 32; j += 8) {
        float v = in[(y0 + ty + j) * 512 + x0 + tx];
        rd[(y0 + ty + j) * 512 + x0 + tx] = v;
        t[ty + j][tx] = v;
    }
    __syncthreads();
#pragma unroll
    for (int j = 0; j < 32; j += 8)
        sd[(x0 + ty + j) * 512 + y0 + tx] = t[tx][ty + j];
}

__global__ __launch_bounds__(256) void ln_kernel(
    float* __restrict__ Pr, const float* __restrict__ g, const float* __restrict__ bta)
{
    const int warp = threadIdx.x >> 5, lane = threadIdx.x & 31;
    const int row = blockIdx.x * 8 + warp;
    const int nb = row >> 10;
    float* p = Pr + (size_t)row * 512;
    float v[16], s = 0.f, sq = 0.f;
#pragma unroll
    for (int i = 0; i < 16; i++) { v[i] = p[lane + 32 * i]; s += v[i]; sq = fmaf(v[i], v[i], sq); }
#pragma unroll
    for (int off = 16; off > 0; off >>= 1) {
        s += __shfl_xor_sync(0xFFFFFFFFu, s, off);
        sq += __shfl_xor_sync(0xFFFFFFFFu, sq, off);
    }
    float mu = s * (1.f / 512.f);
    float r = rsqrtf(sq * (1.f / 512.f) - mu * mu + 1e-5f);
    const float* gg = g + nb * 512;
    const float* bb = bta + nb * 512;
#pragma unroll
    for (int i = 0; i < 16; i++) {
        int d = lane + 32 * i;
        p[d] = fmaf((v[i] - mu) * r, gg[d], bb[d]);
    }
}

// ---------------- launcher ----------------
extern "C" void kernel_launch(void* const* d_in, const int* in_sizes, int n_in,
                              void* d_out, int out_size)
{
    (void)in_sizes; (void)n_in; (void)out_size;
    const float* x_enc = (const float*)d_in[0];
    const float* maskw = (const float*)d_in[4];
    const float* ew1 = (const float*)d_in[5];
    const float* eb1 = (const float*)d_in[6];
    const float* ew2 = (const float*)d_in[7];
    const float* eb2 = (const float*)d_in[8];
    const float* wxh = (const float*)d_in[9];
    const float* whh = (const float*)d_in[10];
    const float* lng = (const float*)d_in[11];
    const float* lnb = (const float*)d_in[12];
    const float* dw1 = (const float*)d_in[13];
    const float* db1 = (const float*)d_in[14];
    const float* dw2 = (const float*)d_in[15];
    const float* db2 = (const float*)d_in[16];
    float* out = (float*)d_out;

    float* S = nullptr;
    cudaGetSymbolAddress((void**)&S, g_scratch);
    float* xn = S + OFF_XN;  float* mnA = S + OFF_MEAN; float* sdA = S + OFF_STD;
    float* Kf = S + OFF_KF;  float* XI = S + OFF_XI;   float* E1 = S + OFF_E1;
    float* E2 = S + OFF_E2;  float* XP = S + OFF_XP;   float* Rb = S + OFF_R;
    float* PR = S + OFF_PR;  float* DH = S + OFF_DH;   float* Sb = S + OFF_S;

    cudaFuncSetAttribute(tc_gemm<0,0,0,false,false>, cudaFuncAttributeMaxDynamicSharedMemorySize, DYNSM);
    cudaFuncSetAttribute(tc_gemm<0,0,0,true,true>,   cudaFuncAttributeMaxDynamicSharedMemorySize, DYNSM);
    cudaFuncSetAttribute(tc_gemm<0,0,0,true,false>,  cudaFuncAttributeMaxDynamicSharedMemorySize, DYNSM);
    cudaFuncSetAttribute(tc_gemm<0,1,0,false,false>, cudaFuncAttributeMaxDynamicSharedMemorySize, DYNSM);
    cudaFuncSetAttribute(tc_gemm<0,2,1,false,false>, cudaFuncAttributeMaxDynamicSharedMemorySize, DYNSM);
    cudaFuncSetAttribute(tc_gemm<1,3,2,false,false>, cudaFuncAttributeMaxDynamicSharedMemorySize, DYNSM);

    const size_t MSZ = 512 * 512;
    auto Rp = [&](int nb, int t) -> float* { return Rb + ((size_t)nb * 12 + t) * MSZ; };
    auto Sp = [&](int nb, int t) -> float* { return Sb + ((size_t)nb * 9 + t) * MSZ; };

    TCArgs ga;
    ga.mean = mnA; ga.stdv = sdA;

    stats_kernel<<<32, 256>>>(x_enc, xn, mnA, sdA);          // launch 0
    filter_kernel<<<4, 512>>>(maskw, Kf);                    // launch 1
    prep_R<<<dim3(16, 16, 4), 256>>>(whh, Rb, Sb);           // launch 2

    // conv as GEMM: C[bc, l] = sum_l' xn[bc,l'] * tap[(l-l')&511] -> XI scatter
    for (int nb = 0; nb < 4; nb++) {
        ga.A[nb] = xn;
        ga.B[nb] = Kf + nb * 512;
        ga.C[nb] = XI + (size_t)nb * (2048u * 2048u);
    }
    tc_gemm<0,2,1,false,false><<<dim3(4,64,4), 256, DYNSM>>>(ga, 8192, 512, 512);  // launch 3

    // power round 1: R2 = R1*R1 (A=R1,B=S1), S2 = S1*S1 (A=S1,B=R1)
    for (int nb = 0; nb < 4; nb++) {
        ga.A[nb*2+0] = Rp(nb,1); ga.B[nb*2+0] = Sp(nb,1); ga.C[nb*2+0] = Rp(nb,2);
        ga.A[nb*2+1] = Sp(nb,1); ga.B[nb*2+1] = Rp(nb,1); ga.C[nb*2+1] = Sp(nb,2);
    }
    tc_gemm<0,0,0,false,false><<<dim3(4,4,8), 256, DYNSM>>>(ga, 512, 512, 512);    // launch 4

    // enc1: relu(XI @ ew1^T + b1)   <-- launch 5 (ncu capture target)
    for (int nb = 0; nb < 4; nb++) {
        ga.A[nb] = XI + (size_t)nb * (2048u * 2048u);
        ga.B[nb] = ew1 + (size_t)nb * (1024u * 2048u);
        ga.bias[nb] = eb1 + (size_t)nb * 1024u;
        ga.C[nb] = E1 + (size_t)nb * (2048u * 1024u);
    }
    tc_gemm<0,0,0,true,true><<<dim3(8,16,4), 256, DYNSM>>>(ga, 2048, 1024, 2048);

    // power round 2
    for (int nb = 0; nb < 4; nb++) {
        int z = nb * 4;
        ga.A[z+0] = Rp(nb,2); ga.B[z+0] = Sp(nb,1); ga.C[z+0] = Rp(nb,3);
        ga.A[z+1] = Rp(nb,2); ga.B[z+1] = Sp(nb,2); ga.C[z+1] = Rp(nb,4);
        ga.A[z+2] = Sp(nb,1); ga.B[z+2] = Rp(nb,2); ga.C[z+2] = Sp(nb,3);
        ga.A[z+3] = Sp(nb,2); ga.B[z+3] = Rp(nb,2); ga.C[z+3] = Sp(nb,4);
    }
    tc_gemm<0,0,0,false,false><<<dim3(4,4,16), 256, DYNSM>>>(ga, 512, 512, 512);

    // power round 3
    for (int nb = 0; nb < 4; nb++)
        for (int j = 1; j <= 4; j++) {
            int z = nb * 8 + (j - 1);
            ga.A[z] = Rp(nb,4); ga.B[z] = Sp(nb,j); ga.C[z] = Rp(nb,4+j);
            int z2 = nb * 8 + 4 + (j - 1);
            ga.A[z2] = Sp(nb,j); ga.B[z2] = Rp(nb,4); ga.C[z2] = Sp(nb,4+j);
        }
    tc_gemm<0,0,0,false,false><<<dim3(4,4,32), 256, DYNSM>>>(ga, 512, 512, 512);

    // power round 4: R9..R11
    for (int nb = 0; nb < 4; nb++)
        for (int j = 1; j <= 3; j++) {
            int z = nb * 3 + (j - 1);
            ga.A[z] = Rp(nb,8); ga.B[z] = Sp(nb,j); ga.C[z] = Rp(nb,8+j);
        }
    tc_gemm<0,0,0,false,false><<<dim3(4,4,12), 256, DYNSM>>>(ga, 512, 512, 512);

    // enc2
    for (int nb = 0; nb < 4; nb++) {
        ga.A[nb] = E1 + (size_t)nb * (2048u * 1024u);
        ga.B[nb] = ew2 + (size_t)nb * (512u * 1024u);
        ga.bias[nb] = eb2 + (size_t)nb * 512u;
        ga.C[nb] = E2 + (size_t)nb * (2048u * 512u);
    }
    tc_gemm<0,0,0,true,false><<<dim3(4,16,4), 256, DYNSM>>>(ga, 2048, 512, 1024);

    // XP = E2 @ wxh^T
    for (int nb = 0; nb < 4; nb++) {
        ga.A[nb] = E2 + (size_t)nb * (2048u * 512u);
        ga.B[nb] = wxh + (size_t)nb * MSZ;
        ga.C[nb] = XP + (size_t)nb * (2048u * 512u);
    }
    tc_gemm<0,0,0,false,false><<<dim3(4,16,4), 256, DYNSM>>>(ga, 2048, 512, 512);

    // RNN fold: PR[256x2048] = XP[256x4096] @ gathered-R^T
    for (int nb = 0; nb < 4; nb++) {
        ga.A[nb] = XP + (size_t)nb * (2048u * 512u);
        ga.B[nb] = Rb + (size_t)nb * 12 * MSZ;
        ga.C[nb] = PR + (size_t)nb * (256u * 2048u);
    }
    tc_gemm<0,1,0,false,false><<<dim3(16,2,4), 256, DYNSM>>>(ga, 256, 2048, 4096);

    ln_kernel<<<512, 256>>>(PR, lng, lnb);

    // dec1: relu(PR @ dw1^T + b1)
    for (int nb = 0; nb < 4; nb++) {
        ga.A[nb] = PR + (size_t)nb * (256u * 2048u);
        ga.B[nb] = dw1 + (size_t)nb * (1024u * 512u);
        ga.bias[nb] = db1 + (size_t)nb * 1024u;
        ga.C[nb] = DH + (size_t)nb * (1024u * 1024u);
    }
    tc_gemm<0,0,0,true,true><<<dim3(8,8,4), 256, DYNSM>>>(ga, 1024, 1024, 512);

    // dec2 fused with nb-sum + final: K = 4*1024, bias = sum db2, out scaled
    ga.A[0] = DH;        // gather across [4][1024][1024]
    ga.B[0] = dw2;       // gather across [4][2048][1024]
    ga.bias[0] = db2;    // 4 x 2048, summed in epilogue
    ga.C[0] = out;
    tc_gemm<1,3,2,false,false><<<dim3(16,8,1), 256, DYNSM>>>(ga, 1024, 2048, 4096);
}